// round 12
// baseline (speedup 1.0000x reference)
#include <cuda_runtime.h>
#include <math_constants.h>

#define NN    10000
#define EE    160000
#define SNAP  16       // B*T
#define TT    8
#define BB    2
#define CIN   64
#define CC    32
#define SLOTS 96       // padded bucket capacity per node (max degree ~40)
#define XCH   256      // rows per xlr block
#define XPAD  66       // smem row stride (floats): 2-way max bank conflicts

// ---------------- static device scratch (zero-initialized at load) ----------------
__device__ float g_xl[NN * SNAP * CC];       // [n][s][c]
__device__ float g_xr[NN * SNAP * CC];       // [n][s][c]
__device__ float g_loop_sum[NN * 3];
__device__ int   g_cursor[NN];               // per-node in-degree / bucket cursor
__device__ int4  g_bkt[NN * SLOTS];          // {src, attr0, attr1, attr2}

__global__ void k_nop() {}                   // ncu launch-index alignment

// ---------------- build: bucket scatter + loop_sum in ONE kernel ----------------
// cursor/loop_sum are zero at entry of every replay: statically zero-initialized
// for the first run, re-zeroed by k_gatgru's epilogue thereafter (stream-ordered).
__global__ void k_build(const int* __restrict__ ei, const float* __restrict__ ea) {
    int e = blockIdx.x * blockDim.x + threadIdx.x;
    if (e >= EE) return;
    int src = ei[e];
    int dst = ei[EE + e];
    float a0 = ea[e * 3 + 0], a1 = ea[e * 3 + 1], a2 = ea[e * 3 + 2];
    atomicAdd(&g_loop_sum[dst * 3 + 0], a0);
    atomicAdd(&g_loop_sum[dst * 3 + 1], a1);
    atomicAdd(&g_loop_sum[dst * 3 + 2], a2);
    int pos = atomicAdd(&g_cursor[dst], 1);
    g_bkt[dst * SLOTS + pos] =
        make_int4(src, __float_as_int(a0), __float_as_int(a1), __float_as_int(a2));
}

// ---------------- xlr v3: lane = row, zero shuffles ----------------
// Block stages XCH=256 x-rows into padded smem; each lane owns one row,
// streams x (LDS, <=2-way conflict) against broadcast float4 weight reads,
// 64 accumulators per lane, writes its row's xl/xr via STG.128.
__global__ void __launch_bounds__(256) k_xlr(const float* __restrict__ x,
                      const float* __restrict__ W_l, const float* __restrict__ b_l,
                      const float* __restrict__ W_r, const float* __restrict__ b_r) {
    extern __shared__ float sx[];            // [XCH][XPAD]
    __shared__ float4 sW[CIN][16];           // [k][cp] = {wl(2cp),wr(2cp),wl(2cp+1),wr(2cp+1)}
    __shared__ float2 sB[CC];                // {bl, br}

    int tid = threadIdx.x;
    for (int i = tid; i < CIN * 16; i += 256) {
        int k = i >> 4, cp = i & 15;
        sW[k][cp] = make_float4(W_l[k * 32 + 2 * cp],     W_r[k * 32 + 2 * cp],
                                W_l[k * 32 + 2 * cp + 1], W_r[k * 32 + 2 * cp + 1]);
    }
    if (tid < CC) sB[tid] = make_float2(b_l[tid], b_r[tid]);

    int rbase = blockIdx.x * XCH;            // grid 625 exact
    // stage x: coalesced float2 loads
    {
        const float2* xg = (const float2*)(x + (long)rbase * CIN);
        for (int i = tid; i < XCH * 32; i += 256) {
            int row = i >> 5, q = i & 31;
            *(float2*)&sx[row * XPAD + q * 2] = xg[row * 32 + q];
        }
    }
    __syncthreads();

    int w = tid >> 5, lane = tid & 31;
    int rloc = w * 32 + lane;
    int rglob = rbase + rloc;

    float accl[32], accr[32];
#pragma unroll
    for (int c = 0; c < 32; c++) {
        float2 b = sB[c];
        accl[c] = b.x;
        accr[c] = b.y;
    }

    const float* xrow = &sx[rloc * XPAD];
#pragma unroll 4
    for (int k = 0; k < CIN; k++) {
        float xk = xrow[k];
#pragma unroll
        for (int cp = 0; cp < 16; cp++) {
            float4 wv = sW[k][cp];           // broadcast LDS.128
            accl[2 * cp]     += xk * wv.x;
            accr[2 * cp]     += xk * wv.y;
            accl[2 * cp + 1] += xk * wv.z;
            accr[2 * cp + 1] += xk * wv.w;
        }
    }

    int s = rglob / NN, n = rglob - s * NN;
    float4* outl = (float4*)(g_xl + (n * SNAP + s) * 32);
    float4* outr = (float4*)(g_xr + (n * SNAP + s) * 32);
#pragma unroll
    for (int c4 = 0; c4 < 8; c4++) {
        outl[c4] = make_float4(accl[4 * c4], accl[4 * c4 + 1],
                               accl[4 * c4 + 2], accl[4 * c4 + 3]);
        outr[c4] = make_float4(accr[4 * c4], accr[4 * c4 + 1],
                               accr[4 * c4 + 2], accr[4 * c4 + 3]);
    }
}

// Fused GATv2 + GRU: warp per node; ee computed on the fly from bucket attrs.
__global__ void __launch_bounds__(256, 2) k_gatgru(
        const float* __restrict__ W_e,
        const float* __restrict__ att, const float* __restrict__ bias_gat,
        const float* __restrict__ W_ih, const float* __restrict__ W_hh,
        const float* __restrict__ b_ih, const float* __restrict__ b_hh,
        float* __restrict__ out) {
    __shared__ float4 sWA[32][32];     // [h][c] = {wi_r, wh_r, wi_z, wh_z}
    __shared__ float2 sWB[32][32];     // [h][c] = {wi_n, wh_n}
    __shared__ float  sb[6][32];
    __shared__ float2 s_tr[8][8][32];  // [warp][t][c] = {batch0, batch1}

    int tid = threadIdx.x;
    for (int i = tid; i < 1024; i += 256) {
        int c = i & 31, hh = i >> 5;
        sWA[hh][c] = make_float4(W_ih[c * 32 + hh],        W_hh[c * 32 + hh],
                                 W_ih[(32 + c) * 32 + hh], W_hh[(32 + c) * 32 + hh]);
        sWB[hh][c] = make_float2(W_ih[(64 + c) * 32 + hh], W_hh[(64 + c) * 32 + hh]);
    }
    if (tid < 96) {
        int g = tid >> 5, c = tid & 31;
        sb[g][c] = b_ih[tid];
        sb[3 + g][c] = b_hh[tid];
    }
    __syncthreads();

    int w = tid >> 5, lane = tid & 31;
    int n = blockIdx.x * 8 + w;            // grid = NN/8 exact
    int q = lane & 7, g = lane >> 3;

    const float4 at4 = *(const float4*)(att + 4 * q);
    const float4 we0 = *(const float4*)(W_e + 4 * q);
    const float4 we1 = *(const float4*)(W_e + 32 + 4 * q);
    const float4 we2 = *(const float4*)(W_e + 64 + 4 * q);

    int deg = g_cursor[n];
    int end = deg + 1;                     // + self loop (last)
    float inv_cnt = 1.f / fmaxf((float)deg, 1.f);
    float lm0 = g_loop_sum[n * 3 + 0] * inv_cnt;
    float lm1 = g_loop_sum[n * 3 + 1] * inv_cnt;
    float lm2 = g_loop_sum[n * 3 + 2] * inv_cnt;

    float4 xr4[4];
    {
        const float4* p = (const float4*)(g_xr + n * SNAP * 32);
#pragma unroll
        for (int k = 0; k < 4; k++) xr4[k] = p[k * 32 + lane];
    }

    float4 acc[4];
#pragma unroll
    for (int k = 0; k < 4; k++) acc[k] = make_float4(0.f, 0.f, 0.f, 0.f);
    float ssum[4] = {0.f, 0.f, 0.f, 0.f};

    const int4* bkt = g_bkt + n * SLOTS;

#define FETCH_EB(J, EB)                                                     \
    do {                                                                    \
        if ((J) < deg) EB = bkt[(J)];                                       \
        else EB = make_int4(n, __float_as_int(lm0), __float_as_int(lm1),    \
                            __float_as_int(lm2));                           \
    } while (0)

    int4 eb0;
    float4 a[4];
    FETCH_EB(0, eb0);
    {
        const float4* xp = (const float4*)(g_xl + eb0.x * SNAP * 32);
#pragma unroll
        for (int k = 0; k < 4; k++) a[k] = xp[k * 32 + lane];
    }

#define GAT_EDGE(A, EB, VALID)                                              \
    do {                                                                    \
        float a0 = __int_as_float(EB.y);                                    \
        float a1 = __int_as_float(EB.z);                                    \
        float a2 = __int_as_float(EB.w);                                    \
        float4 ev;                                                          \
        ev.x = a0 * we0.x + a1 * we1.x + a2 * we2.x;                        \
        ev.y = a0 * we0.y + a1 * we1.y + a2 * we2.y;                        \
        ev.z = a0 * we0.z + a1 * we1.z + a2 * we2.z;                        \
        ev.w = a0 * we0.w + a1 * we1.w + a2 * we2.w;                        \
        float d[4];                                                         \
        _Pragma("unroll")                                                   \
        for (int k = 0; k < 4; k++) {                                       \
            float v0 = A[k].x + ev.x + xr4[k].x;                            \
            float v1 = A[k].y + ev.y + xr4[k].y;                            \
            float v2 = A[k].z + ev.z + xr4[k].z;                            \
            float v3 = A[k].w + ev.w + xr4[k].w;                            \
            v0 = fmaxf(v0, 0.2f * v0);                                      \
            v1 = fmaxf(v1, 0.2f * v1);                                      \
            v2 = fmaxf(v2, 0.2f * v2);                                      \
            v3 = fmaxf(v3, 0.2f * v3);                                      \
            d[k] = v0 * at4.x + v1 * at4.y + v2 * at4.z + v3 * at4.w;       \
        }                                                                   \
        _Pragma("unroll")                                                   \
        for (int o = 1; o < 8; o <<= 1) {                                   \
            _Pragma("unroll")                                               \
            for (int k = 0; k < 4; k++)                                     \
                d[k] += __shfl_xor_sync(0xffffffffu, d[k], o);              \
        }                                                                   \
        _Pragma("unroll")                                                   \
        for (int k = 0; k < 4; k++) {                                       \
            float wv = (VALID) ? __expf(d[k]) : 0.f;                        \
            ssum[k] += wv;                                                  \
            acc[k].x += wv * A[k].x;                                        \
            acc[k].y += wv * A[k].y;                                        \
            acc[k].z += wv * A[k].z;                                        \
            acc[k].w += wv * A[k].w;                                        \
        }                                                                   \
    } while (0)

    for (int j = 0; j < end; j += 2) {
        int j1 = (j + 1 < end) ? j + 1 : j;
        int4 eb1;
        FETCH_EB(j1, eb1);
        const float4* xp1 = (const float4*)(g_xl + eb1.x * SNAP * 32);
        float4 an[4];
#pragma unroll
        for (int k = 0; k < 4; k++) an[k] = xp1[k * 32 + lane];

        int j2 = (j + 2 < end) ? j + 2 : end - 1;
        int4 eb2;
        FETCH_EB(j2, eb2);
        const float4* xp2 = (const float4*)(g_xl + eb2.x * SNAP * 32);
        float4 a2[4];
#pragma unroll
        for (int k = 0; k < 4; k++) a2[k] = xp2[k * 32 + lane];

        GAT_EDGE(a, eb0, true);
        GAT_EDGE(an, eb1, (j + 1 < end));

#pragma unroll
        for (int k = 0; k < 4; k++) a[k] = a2[k];
        eb0 = eb2;
    }
#undef GAT_EDGE
#undef FETCH_EB

    const float4 bi4 = *(const float4*)(bias_gat + 4 * q);
#pragma unroll
    for (int k = 0; k < 4; k++) {
        float inv = 1.f / ssum[k];
        int s = 4 * k + g;
        int b = s >> 3, t = s & 7;
        float* tp = (float*)&s_tr[w][t][4 * q];
        tp[0 * 2 + b] = acc[k].x * inv + bi4.x;
        tp[1 * 2 + b] = acc[k].y * inv + bi4.y;
        tp[2 * 2 + b] = acc[k].z * inv + bi4.z;
        tp[3 * 2 + b] = acc[k].w * inv + bi4.w;
    }
    __syncwarp();

    // ---- GRU phase: lane = channel c; 2 sequences (b=0, b=1)
    int c = lane;
    float bi0 = sb[0][c], bi1 = sb[1][c], bi2 = sb[2][c];
    float bh0 = sb[3][c], bh1 = sb[4][c], bh2 = sb[5][c];

    float h0 = 0.f, h1 = 0.f;
    for (int t = 0; t < TT; t++) {
        float ir0 = bi0, iz0 = bi1, in0 = bi2, hr0 = bh0, hz0 = bh1, hn0 = bh2;
        float ir1 = bi0, iz1 = bi1, in1 = bi2, hr1 = bh0, hz1 = bh1, hn1 = bh2;
#pragma unroll
        for (int hh = 0; hh < 32; hh++) {
            float2 xv = s_tr[w][t][hh];    // one LDS.64 broadcast: {b0, b1}
            float hv0 = __shfl_sync(0xffffffffu, h0, hh);
            float hv1 = __shfl_sync(0xffffffffu, h1, hh);
            float4 wA = sWA[hh][c];
            float2 wB = sWB[hh][c];
            ir0 += xv.x * wA.x; hr0 += hv0 * wA.y;
            iz0 += xv.x * wA.z; hz0 += hv0 * wA.w;
            in0 += xv.x * wB.x; hn0 += hv0 * wB.y;
            ir1 += xv.y * wA.x; hr1 += hv1 * wA.y;
            iz1 += xv.y * wA.z; hz1 += hv1 * wA.w;
            in1 += xv.y * wB.x; hn1 += hv1 * wB.y;
        }
        {
            float r = 1.f / (1.f + __expf(-(ir0 + hr0)));
            float z = 1.f / (1.f + __expf(-(iz0 + hz0)));
            float pre = in0 + r * hn0;
            float e2 = __expf(-2.f * pre);
            float nn_ = 2.f / (1.f + e2) - 1.f;
            h0 = (1.f - z) * nn_ + z * h0;
            out[((long)t * NN + n) * 32 + c] = h0;
        }
        {
            float r = 1.f / (1.f + __expf(-(ir1 + hr1)));
            float z = 1.f / (1.f + __expf(-(iz1 + hz1)));
            float pre = in1 + r * hn1;
            float e2 = __expf(-2.f * pre);
            float nn_ = 2.f / (1.f + e2) - 1.f;
            h1 = (1.f - z) * nn_ + z * h1;
            out[((long)(TT + t) * NN + n) * 32 + c] = h1;
        }
    }

    // epilogue: re-zero per-node counters for the NEXT replay (this warp owns n)
    if (lane < 3) g_loop_sum[n * 3 + lane] = 0.f;
    else if (lane == 3) g_cursor[n] = 0;
}

// ---------------- launch: dummy + 3 kernels, xlr forked ----------------
extern "C" void kernel_launch(void* const* d_in, const int* in_sizes, int n_in,
                              void* d_out, int out_size) {
    const float* x        = (const float*)d_in[0];
    const int*   ei       = (const int*)d_in[1];
    const float* eattr    = (const float*)d_in[2];
    const float* W_l      = (const float*)d_in[3];
    const float* b_l      = (const float*)d_in[4];
    const float* W_r      = (const float*)d_in[5];
    const float* b_r      = (const float*)d_in[6];
    const float* W_e      = (const float*)d_in[7];
    const float* att      = (const float*)d_in[8];
    const float* bias_gat = (const float*)d_in[9];
    const float* W_ih     = (const float*)d_in[10];
    const float* W_hh     = (const float*)d_in[11];
    const float* b_ih     = (const float*)d_in[12];
    const float* b_hh     = (const float*)d_in[13];
    float* out = (float*)d_out;

    static cudaStream_t s1 = nullptr;
    static cudaEvent_t eRoot = nullptr, eXlr = nullptr;
    if (s1 == nullptr) {
        cudaStreamCreateWithFlags(&s1, cudaStreamNonBlocking);
        cudaEventCreateWithFlags(&eRoot, cudaEventDisableTiming);
        cudaEventCreateWithFlags(&eXlr, cudaEventDisableTiming);
        // one-time (uncaptured first call): opt in to 66KB dynamic smem
        cudaFuncSetAttribute(k_xlr, cudaFuncAttributeMaxDynamicSharedMemorySize,
                             XCH * XPAD * (int)sizeof(float));
    }

    k_nop<<<1, 32>>>();   // shifts launch period so ncu -s5 lands on k_gatgru

    // branch: xlr depends only on inputs
    cudaEventRecord(eRoot, 0);
    cudaStreamWaitEvent(s1, eRoot, 0);
    k_xlr<<<SNAP * NN / XCH, 256, XCH * XPAD * sizeof(float), s1>>>(x, W_l, b_l, W_r, b_r);
    cudaEventRecord(eXlr, s1);

    // main: single bucket-build kernel (counters pre-zeroed by prior replay)
    k_build<<<(EE + 255) / 256, 256>>>(ei, eattr);

    cudaStreamWaitEvent(0, eXlr, 0);
    k_gatgru<<<NN / 8, 256>>>(W_e, att, bias_gat, W_ih, W_hh, b_ih, b_hh, out);
}